// round 1
// baseline (speedup 1.0000x reference)
#include <cuda_runtime.h>

// Problem constants (fixed shapes per reference)
#define B_      2048
#define D_      512
#define NA_     512
#define CAP_    32      // bucket capacity per attribute (Poisson(4) tail ~0)
#define NVMAX_  16      // max vectors processed per matrix pass

// ---------------- device scratch (no allocations allowed) ----------------
__device__ int g_counts[NA_];
__device__ int g_buckets[NA_ * CAP_];
__device__ int g_ovf_count;
__device__ int g_ovf[B_];

// ---------------- kernel 0: reset scratch (runs every launch) ------------
__global__ void k_zero() {
    int t = threadIdx.x;
    if (t < NA_) g_counts[t] = 0;
    if (t == 0)  g_ovf_count = 0;
}

// ---------------- kernel 1: bucket samples by attribute ------------------
__global__ void k_bucket(const int* __restrict__ attrs) {
    int b = blockIdx.x * blockDim.x + threadIdx.x;
    if (b >= B_) return;
    int a = attrs[b];
    int pos = atomicAdd(&g_counts[a], 1);
    if (pos < CAP_) {
        g_buckets[a * CAP_ + pos] = b;
    } else {
        int o = atomicAdd(&g_ovf_count, 1);
        g_ovf[o] = b;
    }
}

// ---------------- multi-vector row-dot (templated on vector count) -------
template <int NV>
__device__ __forceinline__ void mv_chunk(
    const float4* __restrict__ mr,     // this thread's matrix row (global), 128 float4
    const float4* __restrict__ sv,     // smem vectors, [NV][128] float4 (zero-padded)
    int nv,                            // actual live vectors (<= NV)
    const int* __restrict__ ssamp,     // smem sample indices
    float* __restrict__ out, int row)
{
    float acc[NV];
#pragma unroll
    for (int j = 0; j < NV; j++) acc[j] = 0.0f;

#pragma unroll 2
    for (int k = 0; k < D_ / 4; k++) {
        float4 m = mr[k];
#pragma unroll
        for (int j = 0; j < NV; j++) {
            float4 v = sv[j * (D_ / 4) + k];   // uniform address -> smem broadcast
            acc[j] += m.x * v.x;
            acc[j] += m.y * v.y;
            acc[j] += m.z * v.z;
            acc[j] += m.w * v.w;
        }
    }
    for (int j = 0; j < nv; j++) {
        float r = acc[j];
        out[(size_t)ssamp[j] * D_ + row] = (r > 0.0f) ? r : 0.0f;
    }
}

// ---------------- kernel 2: per-attribute multi-vector matvec ------------
// grid = (NA_, 4): blockIdx.x = attribute, blockIdx.y = 128-row slice
// block = 128 threads: thread t owns matrix row (blockIdx.y*128 + t)
__global__ __launch_bounds__(128) void k_compute(
    const int*   __restrict__ objs,
    const float* __restrict__ attr_ops,
    const float* __restrict__ obj_emb,
    float*       __restrict__ out)
{
    __shared__ float sv[NVMAX_ * D_];
    __shared__ int   ssamp[NVMAX_];

    int a = blockIdx.x;
    int cnt = g_counts[a];
    if (cnt > CAP_) cnt = CAP_;
    if (cnt == 0) return;

    int tid = threadIdx.x;
    int row = blockIdx.y * 128 + tid;
    const float4* mr =
        (const float4*)(attr_ops + (size_t)a * D_ * D_ + (size_t)row * D_);

    for (int base = 0; base < cnt; base += NVMAX_) {
        int nv = cnt - base;
        if (nv > NVMAX_) nv = NVMAX_;
        int NVsel = (nv <= 1) ? 1 : (nv <= 2) ? 2 : (nv <= 4) ? 4 : (nv <= 8) ? 8 : 16;

        __syncthreads();                       // smem reuse guard across chunks
        if (tid < nv) ssamp[tid] = g_buckets[a * CAP_ + base + tid];
        __syncthreads();

        // cooperative load of nv vectors into smem; zero-pad to NVsel
        for (int j = 0; j < NVsel; j++) {
            float4 val;
            if (j < nv) {
                int s = ssamp[j];
                int o = objs[s];                              // broadcast read
                val = ((const float4*)(obj_emb + (size_t)o * D_))[tid];
            } else {
                val = make_float4(0.f, 0.f, 0.f, 0.f);
            }
            ((float4*)sv)[j * (D_ / 4) + tid] = val;
        }
        __syncthreads();

        switch (NVsel) {
            case 1:  mv_chunk<1> (mr, (const float4*)sv, nv, ssamp, out, row); break;
            case 2:  mv_chunk<2> (mr, (const float4*)sv, nv, ssamp, out, row); break;
            case 4:  mv_chunk<4> (mr, (const float4*)sv, nv, ssamp, out, row); break;
            case 8:  mv_chunk<8> (mr, (const float4*)sv, nv, ssamp, out, row); break;
            default: mv_chunk<16>(mr, (const float4*)sv, nv, ssamp, out, row); break;
        }
    }
}

// ---------------- kernel 3: overflow fallback (per-sample matvec) --------
// Launched with B_ blocks; blocks beyond g_ovf_count exit immediately.
__global__ __launch_bounds__(256) void k_ovf(
    const int*   __restrict__ attrs,
    const int*   __restrict__ objs,
    const float* __restrict__ attr_ops,
    const float* __restrict__ obj_emb,
    float*       __restrict__ out)
{
    int i = blockIdx.x;
    if (i >= g_ovf_count) return;

    __shared__ float sv[D_];
    int b = g_ovf[i];
    int a = attrs[b];
    int o = objs[b];
    int tid = threadIdx.x;

    sv[tid]       = obj_emb[(size_t)o * D_ + tid];
    sv[tid + 256] = obj_emb[(size_t)o * D_ + tid + 256];
    __syncthreads();

    const float* M = attr_ops + (size_t)a * D_ * D_;
#pragma unroll
    for (int rr = 0; rr < 2; rr++) {
        int row = tid + rr * 256;
        const float4* mr = (const float4*)(M + (size_t)row * D_);
        float acc = 0.0f;
#pragma unroll 4
        for (int k = 0; k < D_ / 4; k++) {
            float4 m = mr[k];
            float4 v = ((const float4*)sv)[k];
            acc += m.x * v.x + m.y * v.y + m.z * v.z + m.w * v.w;
        }
        out[(size_t)b * D_ + row] = (acc > 0.0f) ? acc : 0.0f;
    }
}

// ---------------- launch -------------------------------------------------
extern "C" void kernel_launch(void* const* d_in, const int* in_sizes, int n_in,
                              void* d_out, int out_size)
{
    const int*   attrs    = (const int*)d_in[0];
    const int*   objs     = (const int*)d_in[1];
    const float* attr_ops = (const float*)d_in[2];
    const float* obj_emb  = (const float*)d_in[3];
    float*       out      = (float*)d_out;

    k_zero<<<1, 512>>>();
    k_bucket<<<(B_ + 255) / 256, 256>>>(attrs);
    k_compute<<<dim3(NA_, 4), 128>>>(objs, attr_ops, obj_emb, out);
    k_ovf<<<B_, 256>>>(attrs, objs, attr_ops, obj_emb, out);
}

// round 2
// speedup vs baseline: 1.2155x; 1.2155x over previous
#include <cuda_runtime.h>

// Problem constants (fixed shapes per reference)
#define B_      2048
#define D_      512
#define NA_     512
#define CAP_    32      // bucket capacity per attribute (Poisson(4) tail ~0)
#define NVMAX_  16      // max vectors per matrix pass
#define NSL_    8       // row slices per matrix
#define RPC_    64      // rows per CTA (D_/NSL_)
#define RPW_    8       // rows per warp (RPC_/8 warps)

// ---------------- device scratch ----------------
__device__ int g_counts[NA_];
__device__ int g_buckets[NA_ * CAP_];
__device__ int g_ovf_count;
__device__ int g_ovf[B_];

// ---------------- kernel 0: reset ----------------
__global__ void k_zero() {
    int t = threadIdx.x;
    if (t < NA_) g_counts[t] = 0;
    if (t == 0)  g_ovf_count = 0;
}

// ---------------- kernel 1: bucket by attribute ----------------
__global__ void k_bucket(const int* __restrict__ attrs) {
    int b = blockIdx.x * blockDim.x + threadIdx.x;
    if (b >= B_) return;
    int a = attrs[b];
    int pos = atomicAdd(&g_counts[a], 1);
    if (pos < CAP_) {
        g_buckets[a * CAP_ + pos] = b;
    } else {
        int o = atomicAdd(&g_ovf_count, 1);
        g_ovf[o] = b;
    }
}

// ---------------- warp-per-row multi-vector dot ----------------
// Warp loads its matrix row COALESCED (4x LDG.128, lanes contiguous),
// each lane holds 16 k-values; per sample j: lane partial dot from smem
// vector (conflict-free LDS.128), butterfly reduce, lane j stores to smem.
template <int NV>
__device__ __forceinline__ void compute_slice(
    const float* __restrict__ M,       // attr matrix base (global)
    const float4* __restrict__ sv4,    // smem vectors [NV][128] float4
    float* __restrict__ sout,          // smem out stage [NV][RPC_]
    int nv, int row0, int warp, int lane)
{
#pragma unroll 2
    for (int r = 0; r < RPW_; r++) {
        int lrow = warp * RPW_ + r;
        const float4* mrow = (const float4*)(M + (size_t)(row0 + lrow) * D_);
        float4 m0 = mrow[lane];          // k =   0..127 (lane*4 within)
        float4 m1 = mrow[32 + lane];     // k = 128..255
        float4 m2 = mrow[64 + lane];     // k = 256..383
        float4 m3 = mrow[96 + lane];     // k = 384..511

#pragma unroll
        for (int j = 0; j < NV; j++) {
            float4 v0 = sv4[j * 128 + lane];
            float4 v1 = sv4[j * 128 + 32 + lane];
            float4 v2 = sv4[j * 128 + 64 + lane];
            float4 v3 = sv4[j * 128 + 96 + lane];
            float x = m0.x * v0.x;
            x = fmaf(m0.y, v0.y, x);
            x = fmaf(m0.z, v0.z, x);
            x = fmaf(m0.w, v0.w, x);
            x = fmaf(m1.x, v1.x, x);
            x = fmaf(m1.y, v1.y, x);
            x = fmaf(m1.z, v1.z, x);
            x = fmaf(m1.w, v1.w, x);
            x = fmaf(m2.x, v2.x, x);
            x = fmaf(m2.y, v2.y, x);
            x = fmaf(m2.z, v2.z, x);
            x = fmaf(m2.w, v2.w, x);
            x = fmaf(m3.x, v3.x, x);
            x = fmaf(m3.y, v3.y, x);
            x = fmaf(m3.z, v3.z, x);
            x = fmaf(m3.w, v3.w, x);
            // butterfly reduce across 32 lanes
            x += __shfl_xor_sync(0xffffffffu, x, 16);
            x += __shfl_xor_sync(0xffffffffu, x, 8);
            x += __shfl_xor_sync(0xffffffffu, x, 4);
            x += __shfl_xor_sync(0xffffffffu, x, 2);
            x += __shfl_xor_sync(0xffffffffu, x, 1);
            if (j < nv && lane == j)
                sout[j * RPC_ + lrow] = (x > 0.0f) ? x : 0.0f;
        }
    }
}

// ---------------- kernel 2: per-attribute multi-vector matvec ----------
// grid = (NA_, NSL_): x = attribute, y = 64-row slice. 256 threads.
__global__ __launch_bounds__(256) void k_compute(
    const int*   __restrict__ objs,
    const float* __restrict__ attr_ops,
    const float* __restrict__ obj_emb,
    float*       __restrict__ out)
{
    __shared__ float sv[NVMAX_ * D_];      // 32 KB
    __shared__ float sout[NVMAX_ * RPC_];  // 4 KB
    __shared__ int   ssamp[NVMAX_];

    int a = blockIdx.x;
    int cnt = g_counts[a];
    if (cnt > CAP_) cnt = CAP_;
    if (cnt == 0) return;

    int tid  = threadIdx.x;
    int lane = tid & 31;
    int warp = tid >> 5;
    int row0 = blockIdx.y * RPC_;
    const float* M = attr_ops + (size_t)a * D_ * D_;

    for (int base = 0; base < cnt; base += NVMAX_) {
        int nv = cnt - base;
        if (nv > NVMAX_) nv = NVMAX_;
        int NVsel = (nv <= 1) ? 1 : (nv <= 2) ? 2 : (nv <= 4) ? 4 : (nv <= 8) ? 8 : 16;

        __syncthreads();   // smem reuse guard across passes
        if (tid < nv) ssamp[tid] = g_buckets[a * CAP_ + base + tid];
        __syncthreads();

        // cooperative vector load: 2 vectors per 256-thread pass
        for (int j = tid >> 7; j < nv; j += 2) {
            int o = objs[ssamp[j]];                            // broadcast
            ((float4*)sv)[j * 128 + (tid & 127)] =
                ((const float4*)(obj_emb + (size_t)o * D_))[tid & 127];
        }
        __syncthreads();

        switch (NVsel) {
            case 1:  compute_slice<1> (M, (const float4*)sv, sout, nv, row0, warp, lane); break;
            case 2:  compute_slice<2> (M, (const float4*)sv, sout, nv, row0, warp, lane); break;
            case 4:  compute_slice<4> (M, (const float4*)sv, sout, nv, row0, warp, lane); break;
            case 8:  compute_slice<8> (M, (const float4*)sv, sout, nv, row0, warp, lane); break;
            default: compute_slice<16>(M, (const float4*)sv, sout, nv, row0, warp, lane); break;
        }
        __syncthreads();

        // coalesced write-out: 64 contiguous floats per sample slice
        for (int idx = tid; idx < nv * RPC_; idx += 256) {
            int j  = idx >> 6;
            int rl = idx & 63;
            out[(size_t)ssamp[j] * D_ + row0 + rl] = sout[idx];
        }
    }
}

// ---------------- kernel 3: overflow fallback (grid-stride) ------------
__global__ __launch_bounds__(256) void k_ovf(
    const int*   __restrict__ attrs,
    const int*   __restrict__ objs,
    const float* __restrict__ attr_ops,
    const float* __restrict__ obj_emb,
    float*       __restrict__ out)
{
    __shared__ float sv[D_];
    int n = g_ovf_count;
    for (int i = blockIdx.x; i < n; i += gridDim.x) {
        int b = g_ovf[i];
        int a = attrs[b];
        int o = objs[b];
        int tid = threadIdx.x;

        __syncthreads();
        sv[tid]       = obj_emb[(size_t)o * D_ + tid];
        sv[tid + 256] = obj_emb[(size_t)o * D_ + tid + 256];
        __syncthreads();

        const float* M = attr_ops + (size_t)a * D_ * D_;
#pragma unroll
        for (int rr = 0; rr < 2; rr++) {
            int row = tid + rr * 256;
            const float4* mr = (const float4*)(M + (size_t)row * D_);
            float acc = 0.0f;
#pragma unroll 4
            for (int k = 0; k < D_ / 4; k++) {
                float4 m = mr[k];
                float4 v = ((const float4*)sv)[k];
                acc += m.x * v.x + m.y * v.y + m.z * v.z + m.w * v.w;
            }
            out[(size_t)b * D_ + row] = (acc > 0.0f) ? acc : 0.0f;
        }
    }
}

// ---------------- launch -------------------------------------------------
extern "C" void kernel_launch(void* const* d_in, const int* in_sizes, int n_in,
                              void* d_out, int out_size)
{
    const int*   attrs    = (const int*)d_in[0];
    const int*   objs     = (const int*)d_in[1];
    const float* attr_ops = (const float*)d_in[2];
    const float* obj_emb  = (const float*)d_in[3];
    float*       out      = (float*)d_out;

    k_zero<<<1, 512>>>();
    k_bucket<<<(B_ + 255) / 256, 256>>>(attrs);
    k_compute<<<dim3(NA_, NSL_), 256>>>(objs, attr_ops, obj_emb, out);
    k_ovf<<<64, 256>>>(attrs, objs, attr_ops, obj_emb, out);
}